// round 2
// baseline (speedup 1.0000x reference)
#include <cuda_runtime.h>
#include <math.h>

#define NN 50000
#define EE 800000

// ---------------- scratch (static __device__, no runtime allocation) ----------------
__device__ float g_dis[NN];          // degree^-1/2 (includes +1 self loop)
__device__ int   g_rows[EE];
__device__ int   g_cols[EE];
__device__ float g_enorm[EE];        // dis[row]*dis[col]
__device__ float g_Afc[NN * 192];    // Agg([feature | condition])
__device__ float g_H2 [NN * 256];    // [f2h | c2h]
__device__ float g_HD [NN * 256];    // [z2h | c2h_d]
__device__ float g_P  [NN * 64];     // h @ [W_mean | W_logvar]   (pre-agg)
__device__ float g_Aml[NN * 64];     // Agg(P) + bias  -> mean|logvar
__device__ float g_Az [NN * 32];     // Agg(z)
__device__ float g_O  [NN * 128];    // hd @ W_out (pre-agg)
__device__ float g_Wml[256 * 64];    // [W_mean | W_logvar] packed
__device__ int   g_is64;

// ---------------- small helpers ----------------
__global__ void k_init_deg(int n) {
    int i = blockIdx.x * 256 + threadIdx.x;
    if (i < n) g_dis[i] = 1.0f;   // self-loop contribution to degree
}

__global__ void k_detect(const long long* p, int e, int n) {
    __shared__ int ok;
    if (threadIdx.x == 0) ok = 1;
    __syncthreads();
    int stride = e / 256; if (stride < 1) stride = 1;
    long long v = p[(long long)threadIdx.x * stride];
    if (v < 0 || v >= (long long)n) ok = 0;
    __syncthreads();
    if (threadIdx.x == 0) g_is64 = ok;
}

__global__ void k_convert(const void* p, int e) {
    int i = blockIdx.x * 256 + threadIdx.x;
    if (i >= e) return;
    int r, c;
    if (g_is64) {
        const long long* q = (const long long*)p;
        r = (int)q[i]; c = (int)q[e + i];
    } else {
        const int* q = (const int*)p;
        r = q[i]; c = q[e + i];
    }
    g_rows[i] = r;
    g_cols[i] = c;
    atomicAdd(&g_dis[c], 1.0f);
}

__global__ void k_rsqrt(int n) {
    int i = blockIdx.x * 256 + threadIdx.x;
    if (i < n) g_dis[i] = rsqrtf(g_dis[i]);
}

__global__ void k_enorm(int e) {
    int i = blockIdx.x * 256 + threadIdx.x;
    if (i < e) g_enorm[i] = g_dis[g_rows[i]] * g_dis[g_cols[i]];
}

__global__ void k_pack_wml(const float* __restrict__ Wm, const float* __restrict__ Wl) {
    int idx = blockIdx.x * 256 + threadIdx.x;
    if (idx >= 256 * 64) return;
    int k = idx / 64, j = idx % 64;
    g_Wml[idx] = (j < 32) ? Wm[k * 32 + j] : Wl[k * 32 + (j - 32)];
}

// ---------------- edge aggregation: dst[col] += src[row] * enorm ----------------
template<int C0, int C1>
__global__ void k_agg(const float4* __restrict__ s0, const float4* __restrict__ s1,
                      float4* __restrict__ dst, int e) {
    constexpr int CT = C0 + C1;
    int idx = blockIdx.x * 256 + threadIdx.x;
    if (idx >= e * CT) return;
    int ed = idx / CT, c = idx % CT;
    int r   = g_rows[ed];
    int col = g_cols[ed];
    float w = g_enorm[ed];
    float4 v;
    if (C1 == 0 || c < C0) v = s0[r * C0 + c];
    else                   v = s1[r * C1 + (c - C0)];
    float* p = (float*)&dst[col * CT + c];
    asm volatile("red.global.add.v4.f32 [%0], {%1, %2, %3, %4};"
                 :: "l"(p), "f"(v.x * w), "f"(v.y * w), "f"(v.z * w), "f"(v.w * w)
                 : "memory");
}

// ---------------- init kernels (self-loop term, + bias where it belongs) ----------------
__global__ void k_init_afc(const float4* __restrict__ feat, const float4* __restrict__ cond, int n) {
    int idx = blockIdx.x * 256 + threadIdx.x;
    if (idx >= n * 48) return;
    int i = idx / 48, c = idx % 48;
    float d = g_dis[i]; float d2 = d * d;
    float4 v = (c < 32) ? feat[i * 32 + c] : cond[i * 16 + (c - 32)];
    float4 o; o.x = v.x * d2; o.y = v.y * d2; o.z = v.z * d2; o.w = v.w * d2;
    ((float4*)g_Afc)[idx] = o;
}

__global__ void k_init_aml(const float* __restrict__ b_mean, const float* __restrict__ b_lv, int n) {
    int idx = blockIdx.x * 256 + threadIdx.x;
    if (idx >= n * 64) return;
    int i = idx / 64, j = idx % 64;
    float d = g_dis[i];
    float b = (j < 32) ? b_mean[j] : b_lv[j - 32];
    g_Aml[idx] = g_P[idx] * d * d + b;
}

__global__ void k_z(const float* __restrict__ noise,
                    float* __restrict__ oz, float* __restrict__ om,
                    float* __restrict__ olv, int n) {
    int idx = blockIdx.x * 256 + threadIdx.x;
    if (idx >= n * 32) return;
    int i = idx / 32;
    int j = idx % 32;
    float m  = g_Aml[i * 64 + j];
    float lv = g_Aml[i * 64 + 32 + j];
    float z  = noise[idx] * expf(0.5f * lv) + m;
    oz[idx]  = z;
    om[idx]  = m;
    olv[idx] = lv;
    float d = g_dis[i];
    g_Az[idx] = z * d * d;
}

__global__ void k_init_out(const float4* __restrict__ bout, float4* __restrict__ oo, int n) {
    int idx = blockIdx.x * 256 + threadIdx.x;
    if (idx >= n * 32) return;
    int i = idx / 32, c = idx % 32;
    float d = g_dis[i]; float d2 = d * d;
    float4 v = ((const float4*)g_O)[idx];
    float4 b = bout[c];
    float4 o;
    o.x = v.x * d2 + b.x; o.y = v.y * d2 + b.y;
    o.z = v.z * d2 + b.z; o.w = v.w * d2 + b.w;
    oo[idx] = o;
}

// ---------------- tiled GEMM: C[M,NC] = A[M,K] @ W[K,NC] (+bias) (tanh) ----------------
// 256 threads, 8x8 register microtile, K-chunk 16.
template<int K, int NC, bool BIAS, bool TANH>
__global__ __launch_bounds__(256, 2) void k_gemm8(
    const float* __restrict__ A, int lda,
    const float* __restrict__ W, const float* __restrict__ bias,
    float* __restrict__ C, int ldc, int M)
{
    constexpr int COLT = NC / 8;        // threads along columns
    constexpr int ROWT = 256 / COLT;    // threads along rows
    constexpr int TM   = ROWT * 8;      // rows per block
    constexpr int LDA_S = TM + 4;       // padded row for sA (16B aligned)
    __shared__ float sA[16][LDA_S];
    __shared__ float sW[16][NC];

    int tid = threadIdx.x;
    int m0  = blockIdx.x * TM;
    int tx  = tid % COLT, ty = tid / COLT;
    int c0  = tx * 8, r0 = ty * 8;

    float acc[8][8];
    #pragma unroll
    for (int i = 0; i < 8; i++)
        #pragma unroll
        for (int j = 0; j < 8; j++) acc[i][j] = 0.0f;

    for (int k0 = 0; k0 < K; k0 += 16) {
        // load A tile transposed: sA[kk][row]. TM*4 float4 total.
        #pragma unroll
        for (int f = tid; f < TM * 4; f += 256) {
            int r = f >> 2, kk4 = (f & 3) * 4;
            float4 av = make_float4(0.f, 0.f, 0.f, 0.f);
            int gr = m0 + r;
            if (gr < M) av = *(const float4*)&A[(size_t)gr * lda + k0 + kk4];
            sA[kk4 + 0][r] = av.x;
            sA[kk4 + 1][r] = av.y;
            sA[kk4 + 2][r] = av.z;
            sA[kk4 + 3][r] = av.w;
        }
        // load W tile: sW[kk][col]. 16*NC/4 float4 total.
        #pragma unroll
        for (int f = tid; f < 4 * NC; f += 256) {
            int kk = f / (NC / 4), c4 = f % (NC / 4);
            *(float4*)&sW[kk][c4 * 4] = *(const float4*)&W[(size_t)(k0 + kk) * NC + c4 * 4];
        }
        __syncthreads();
        #pragma unroll
        for (int kk = 0; kk < 16; kk++) {
            float4 a0 = *(const float4*)&sA[kk][r0];
            float4 a1 = *(const float4*)&sA[kk][r0 + 4];
            float4 w0 = *(const float4*)&sW[kk][c0];
            float4 w1 = *(const float4*)&sW[kk][c0 + 4];
            float av[8] = {a0.x, a0.y, a0.z, a0.w, a1.x, a1.y, a1.z, a1.w};
            float wv[8] = {w0.x, w0.y, w0.z, w0.w, w1.x, w1.y, w1.z, w1.w};
            #pragma unroll
            for (int i = 0; i < 8; i++)
                #pragma unroll
                for (int j = 0; j < 8; j++)
                    acc[i][j] += av[i] * wv[j];
        }
        __syncthreads();
    }

    float4 bv0 = make_float4(0.f, 0.f, 0.f, 0.f);
    float4 bv1 = make_float4(0.f, 0.f, 0.f, 0.f);
    if (BIAS) {
        bv0 = *(const float4*)&bias[c0];
        bv1 = *(const float4*)&bias[c0 + 4];
    }
    #pragma unroll
    for (int i = 0; i < 8; i++) {
        int gr = m0 + r0 + i;
        if (gr >= M) continue;
        float4 o0, o1;
        o0.x = acc[i][0] + bv0.x; o0.y = acc[i][1] + bv0.y;
        o0.z = acc[i][2] + bv0.z; o0.w = acc[i][3] + bv0.w;
        o1.x = acc[i][4] + bv1.x; o1.y = acc[i][5] + bv1.y;
        o1.z = acc[i][6] + bv1.z; o1.w = acc[i][7] + bv1.w;
        if (TANH) {
            o0.x = tanhf(o0.x); o0.y = tanhf(o0.y); o0.z = tanhf(o0.z); o0.w = tanhf(o0.w);
            o1.x = tanhf(o1.x); o1.y = tanhf(o1.y); o1.z = tanhf(o1.z); o1.w = tanhf(o1.w);
        }
        *(float4*)&C[(size_t)gr * ldc + c0]     = o0;
        *(float4*)&C[(size_t)gr * ldc + c0 + 4] = o1;
    }
}

// ---------------- launch ----------------
static inline int cdiv(int a, int b) { return (a + b - 1) / b; }

extern "C" void kernel_launch(void* const* d_in, const int* in_sizes, int n_in,
                              void* d_out, int out_size) {
    const float* feature   = (const float*)d_in[0];
    const float* condition = (const float*)d_in[1];
    const float* noise     = (const float*)d_in[2];
    const float* W_f2h     = (const float*)d_in[3];
    const float* b_f2h     = (const float*)d_in[4];
    const float* W_c2h_e   = (const float*)d_in[5];
    const float* b_c2h_e   = (const float*)d_in[6];
    const float* W_mean    = (const float*)d_in[7];
    const float* b_mean    = (const float*)d_in[8];
    const float* W_logvar  = (const float*)d_in[9];
    const float* b_logvar  = (const float*)d_in[10];
    const float* W_z2h     = (const float*)d_in[11];
    const float* b_z2h     = (const float*)d_in[12];
    const float* W_c2h_d   = (const float*)d_in[13];
    const float* b_c2h_d   = (const float*)d_in[14];
    const float* W_out     = (const float*)d_in[15];
    const float* b_out     = (const float*)d_in[16];
    const void*  eidx      = d_in[17];

    int n = in_sizes[0] / 128;
    int e = in_sizes[17] / 2;

    float* oz  = (float*)d_out;
    float* om  = oz  + (size_t)n * 32;
    float* olv = om  + (size_t)n * 32;
    float* oo  = olv + (size_t)n * 32;

    void *pAfc, *pH2, *pHD, *pP, *pAml, *pAz, *pO, *pWml;
    cudaGetSymbolAddress(&pAfc, g_Afc);
    cudaGetSymbolAddress(&pH2,  g_H2);
    cudaGetSymbolAddress(&pHD,  g_HD);
    cudaGetSymbolAddress(&pP,   g_P);
    cudaGetSymbolAddress(&pAml, g_Aml);
    cudaGetSymbolAddress(&pAz,  g_Az);
    cudaGetSymbolAddress(&pO,   g_O);
    cudaGetSymbolAddress(&pWml, g_Wml);
    float* Afc = (float*)pAfc;
    float* H2  = (float*)pH2;
    float* HD  = (float*)pHD;
    float* P   = (float*)pP;
    float* Aml = (float*)pAml;
    float* Az  = (float*)pAz;
    float* O   = (float*)pO;
    float* Wml = (float*)pWml;

    // degree + normalization
    k_init_deg<<<cdiv(n, 256), 256>>>(n);
    k_detect<<<1, 256>>>((const long long*)eidx, e, n);
    k_convert<<<cdiv(e, 256), 256>>>(eidx, e);
    k_rsqrt<<<cdiv(n, 256), 256>>>(n);
    k_enorm<<<cdiv(e, 256), 256>>>(e);
    k_pack_wml<<<cdiv(256 * 64, 256), 256>>>(W_mean, W_logvar);

    // Pass A: Agg([feature|condition])  width 192
    k_init_afc<<<cdiv(n * 48, 256), 256>>>((const float4*)feature, (const float4*)condition, n);
    k_agg<32, 16><<<cdiv(e * 48, 256), 256>>>((const float4*)feature, (const float4*)condition,
                                              (float4*)Afc, e);

    // Encoder projections (bias + tanh)
    k_gemm8<128, 128, true, true><<<cdiv(n, 128), 256>>>(Afc,       192, W_f2h,   b_f2h,   H2,       256, n);
    k_gemm8< 64, 128, true, true><<<cdiv(n, 128), 256>>>(Afc + 128, 192, W_c2h_e, b_c2h_e, H2 + 128, 256, n);
    k_gemm8< 64, 128, true, true><<<cdiv(n, 128), 256>>>(Afc + 128, 192, W_c2h_d, b_c2h_d, HD + 128, 256, n);

    // mean+logvar fused projection (bias applied after aggregation)
    k_gemm8<256, 64, false, false><<<cdiv(n, 256), 256>>>(H2, 256, Wml, nullptr, P, 64, n);

    // Pass B: Agg(P) width 64, then z / mean / logvar
    k_init_aml<<<cdiv(n * 64, 256), 256>>>(b_mean, b_logvar, n);
    k_agg<16, 0><<<cdiv(e * 16, 256), 256>>>((const float4*)P, (const float4*)P,
                                             (float4*)Aml, e);
    k_z<<<cdiv(n * 32, 256), 256>>>(noise, oz, om, olv, n);

    // Pass C: Agg(z) width 32
    k_agg<8, 0><<<cdiv(e * 8, 256), 256>>>((const float4*)oz, (const float4*)oz,
                                           (float4*)Az, e);

    // Decoder
    k_gemm8< 32, 128, true,  true ><<<cdiv(n, 128), 256>>>(Az, 32,  W_z2h, b_z2h, HD, 256, n);
    k_gemm8<256, 128, false, false><<<cdiv(n, 128), 256>>>(HD, 256, W_out, nullptr, O, 128, n);

    // Pass D: out = Agg(O) + b_out
    k_init_out<<<cdiv(n * 32, 256), 256>>>((const float4*)b_out, (float4*)oo, n);
    k_agg<32, 0><<<cdiv(e * 32, 256), 256>>>((const float4*)O, (const float4*)O,
                                             (float4*)oo, e);
}

// round 3
// speedup vs baseline: 1.2222x; 1.2222x over previous
#include <cuda_runtime.h>
#include <math.h>

#define NN 50000
#define EE 800000

// ---------------- scratch (static __device__, no runtime allocation) ----------------
__device__ float g_dis[NN];          // (deg+1)^-1/2
__device__ int   g_deg[NN];          // in-degree (edges only)
__device__ int   g_off[NN + 1];      // CSR offsets (by destination col)
__device__ int   g_cur[NN];          // scatter cursors
__device__ int   g_rows[EE];         // raw row per edge
__device__ int   g_cols[EE];         // raw col per edge
__device__ int   g_srows[EE];        // CSR-sorted source row
__device__ float g_senorm[EE];       // CSR-sorted edge weight dis[row]*dis[col]
__device__ float g_Afc[NN * 192];    // Agg([feature | condition])
__device__ float g_H2 [NN * 256];    // [f2h | c2h]
__device__ float g_HD [NN * 256];    // [z2h | c2h_d]
__device__ float g_P  [NN * 64];     // h @ [W_mean | W_logvar]   (pre-agg)
__device__ float g_Aml[NN * 64];     // Agg(P) + bias  -> mean|logvar
__device__ float g_Az [NN * 32];     // Agg(z)
__device__ float g_O  [NN * 128];    // hd @ W_out (pre-agg)
__device__ float g_Wml[256 * 64];    // [W_mean | W_logvar] packed
__device__ float g_bml[64];          // [b_mean | b_logvar] packed
__device__ int   g_is64;

// ---------------- small helpers ----------------
__global__ void k_zero_deg(int n) {
    int i = blockIdx.x * 256 + threadIdx.x;
    if (i < n) g_deg[i] = 0;
}

__global__ void k_detect(const long long* p, int e, int n) {
    __shared__ int ok;
    if (threadIdx.x == 0) ok = 1;
    __syncthreads();
    int stride = e / 256; if (stride < 1) stride = 1;
    long long v = p[(long long)threadIdx.x * stride];
    if (v < 0 || v >= (long long)n) ok = 0;
    __syncthreads();
    if (threadIdx.x == 0) g_is64 = ok;
}

__global__ void k_convert(const void* p, int e) {
    int i = blockIdx.x * 256 + threadIdx.x;
    if (i >= e) return;
    int r, c;
    if (g_is64) {
        const long long* q = (const long long*)p;
        r = (int)q[i]; c = (int)q[e + i];
    } else {
        const int* q = (const int*)p;
        r = q[i]; c = q[e + i];
    }
    g_rows[i] = r;
    g_cols[i] = c;
    atomicAdd(&g_deg[c], 1);
}

__global__ void k_dis(int n) {
    int i = blockIdx.x * 256 + threadIdx.x;
    if (i < n) g_dis[i] = rsqrtf((float)g_deg[i] + 1.0f);
}

// single-block scan of degrees -> offsets + cursors
__global__ void k_scan(int n, int e) {
    __shared__ int part[1024];
    int t = threadIdx.x;
    int chunk = (n + 1023) / 1024;
    int s = t * chunk;
    int en = s + chunk; if (en > n) en = n;
    int sum = 0;
    for (int i = s; i < en; i++) sum += g_deg[i];
    part[t] = sum;
    __syncthreads();
    for (int off = 1; off < 1024; off <<= 1) {
        int v = (t >= off) ? part[t - off] : 0;
        __syncthreads();
        part[t] += v;
        __syncthreads();
    }
    int base = (t == 0) ? 0 : part[t - 1];
    for (int i = s; i < en; i++) {
        g_off[i] = base;
        g_cur[i] = base;
        base += g_deg[i];
    }
    if (t == 1023) g_off[n] = e;
}

__global__ void k_scatter(int e) {
    int i = blockIdx.x * 256 + threadIdx.x;
    if (i >= e) return;
    int r = g_rows[i], c = g_cols[i];
    int pos = atomicAdd(&g_cur[c], 1);
    g_srows[pos]  = r;
    g_senorm[pos] = g_dis[r] * g_dis[c];
}

__global__ void k_pack_wml(const float* __restrict__ Wm, const float* __restrict__ Wl,
                           const float* __restrict__ bm, const float* __restrict__ bl) {
    int idx = blockIdx.x * 256 + threadIdx.x;
    if (idx < 64) g_bml[idx] = (idx < 32) ? bm[idx] : bl[idx - 32];
    if (idx >= 256 * 64) return;
    int k = idx / 64, j = idx % 64;
    g_Wml[idx] = (j < 32) ? Wm[k * 32 + j] : Wl[k * 32 + (j - 32)];
}

// ---------------- CSR aggregation: dst[i] = d_i^2*src[i] + sum_e w_e*src[row_e] (+bias) ----------------
template<int C0, int C1, bool BIAS>
__global__ __launch_bounds__(256) void k_aggc(
    const float4* __restrict__ s0, const float4* __restrict__ s1,
    const float4* __restrict__ bias, float4* __restrict__ dst, int n)
{
    constexpr int CT = C0 + C1;
    int idx = blockIdx.x * 256 + threadIdx.x;
    if (idx >= n * CT) return;
    int i = idx / CT, c = idx % CT;

    const float4* __restrict__ base;
    int stride;
    if (C1 == 0 || c < C0) { base = s0 + c;        stride = C0; }
    else                   { base = s1 + (c - C0); stride = C1; }

    float d = g_dis[i];
    float w0 = d * d;
    float4 v = base[(size_t)i * stride];
    float4 acc;
    acc.x = v.x * w0; acc.y = v.y * w0; acc.z = v.z * w0; acc.w = v.w * w0;

    int b = g_off[i], bend = g_off[i + 1];
    #pragma unroll 4
    for (int eix = b; eix < bend; eix++) {
        int   r = g_srows[eix];
        float w = g_senorm[eix];
        float4 u = base[(size_t)r * stride];
        acc.x += u.x * w; acc.y += u.y * w; acc.z += u.z * w; acc.w += u.w * w;
    }
    if (BIAS) {
        float4 bb = bias[c];
        acc.x += bb.x; acc.y += bb.y; acc.z += bb.z; acc.w += bb.w;
    }
    dst[(size_t)i * CT + c] = acc;
}

// ---------------- z / reparameterization ----------------
__global__ void k_z(const float* __restrict__ noise,
                    float* __restrict__ oz, float* __restrict__ om,
                    float* __restrict__ olv, int n) {
    int idx = blockIdx.x * 256 + threadIdx.x;
    if (idx >= n * 32) return;
    int i = idx / 32;
    int j = idx % 32;
    float m  = g_Aml[i * 64 + j];
    float lv = g_Aml[i * 64 + 32 + j];
    float z  = noise[idx] * expf(0.5f * lv) + m;
    oz[idx]  = z;
    om[idx]  = m;
    olv[idx] = lv;
}

// ---------------- tiled GEMM: C[M,NC] = A[M,K] @ W[K,NC] (+bias) (tanh) ----------------
// 256 threads, 8x8 register microtile, K-chunk 16.
template<int K, int NC, bool BIAS, bool TANH>
__global__ __launch_bounds__(256, 2) void k_gemm8(
    const float* __restrict__ A, int lda,
    const float* __restrict__ W, const float* __restrict__ bias,
    float* __restrict__ C, int ldc, int M)
{
    constexpr int COLT = NC / 8;        // threads along columns
    constexpr int ROWT = 256 / COLT;    // threads along rows
    constexpr int TM   = ROWT * 8;      // rows per block
    constexpr int LDA_S = TM + 4;
    __shared__ float sA[16][LDA_S];
    __shared__ float sW[16][NC];

    int tid = threadIdx.x;
    int m0  = blockIdx.x * TM;
    int tx  = tid % COLT, ty = tid / COLT;
    int c0  = tx * 8, r0 = ty * 8;

    float acc[8][8];
    #pragma unroll
    for (int i = 0; i < 8; i++)
        #pragma unroll
        for (int j = 0; j < 8; j++) acc[i][j] = 0.0f;

    for (int k0 = 0; k0 < K; k0 += 16) {
        #pragma unroll
        for (int f = tid; f < TM * 4; f += 256) {
            int r = f >> 2, kk4 = (f & 3) * 4;
            float4 av = make_float4(0.f, 0.f, 0.f, 0.f);
            int gr = m0 + r;
            if (gr < M) av = *(const float4*)&A[(size_t)gr * lda + k0 + kk4];
            sA[kk4 + 0][r] = av.x;
            sA[kk4 + 1][r] = av.y;
            sA[kk4 + 2][r] = av.z;
            sA[kk4 + 3][r] = av.w;
        }
        #pragma unroll
        for (int f = tid; f < 4 * NC; f += 256) {
            int kk = f / (NC / 4), c4 = f % (NC / 4);
            *(float4*)&sW[kk][c4 * 4] = *(const float4*)&W[(size_t)(k0 + kk) * NC + c4 * 4];
        }
        __syncthreads();
        #pragma unroll
        for (int kk = 0; kk < 16; kk++) {
            float4 a0 = *(const float4*)&sA[kk][r0];
            float4 a1 = *(const float4*)&sA[kk][r0 + 4];
            float4 w0 = *(const float4*)&sW[kk][c0];
            float4 w1 = *(const float4*)&sW[kk][c0 + 4];
            float av[8] = {a0.x, a0.y, a0.z, a0.w, a1.x, a1.y, a1.z, a1.w};
            float wv[8] = {w0.x, w0.y, w0.z, w0.w, w1.x, w1.y, w1.z, w1.w};
            #pragma unroll
            for (int i = 0; i < 8; i++)
                #pragma unroll
                for (int j = 0; j < 8; j++)
                    acc[i][j] += av[i] * wv[j];
        }
        __syncthreads();
    }

    float4 bv0 = make_float4(0.f, 0.f, 0.f, 0.f);
    float4 bv1 = make_float4(0.f, 0.f, 0.f, 0.f);
    if (BIAS) {
        bv0 = *(const float4*)&bias[c0];
        bv1 = *(const float4*)&bias[c0 + 4];
    }
    #pragma unroll
    for (int i = 0; i < 8; i++) {
        int gr = m0 + r0 + i;
        if (gr >= M) continue;
        float4 o0, o1;
        o0.x = acc[i][0] + bv0.x; o0.y = acc[i][1] + bv0.y;
        o0.z = acc[i][2] + bv0.z; o0.w = acc[i][3] + bv0.w;
        o1.x = acc[i][4] + bv1.x; o1.y = acc[i][5] + bv1.y;
        o1.z = acc[i][6] + bv1.z; o1.w = acc[i][7] + bv1.w;
        if (TANH) {
            o0.x = tanhf(o0.x); o0.y = tanhf(o0.y); o0.z = tanhf(o0.z); o0.w = tanhf(o0.w);
            o1.x = tanhf(o1.x); o1.y = tanhf(o1.y); o1.z = tanhf(o1.z); o1.w = tanhf(o1.w);
        }
        *(float4*)&C[(size_t)gr * ldc + c0]     = o0;
        *(float4*)&C[(size_t)gr * ldc + c0 + 4] = o1;
    }
}

// ---------------- launch ----------------
static inline int cdiv(int a, int b) { return (a + b - 1) / b; }

extern "C" void kernel_launch(void* const* d_in, const int* in_sizes, int n_in,
                              void* d_out, int out_size) {
    const float* feature   = (const float*)d_in[0];
    const float* condition = (const float*)d_in[1];
    const float* noise     = (const float*)d_in[2];
    const float* W_f2h     = (const float*)d_in[3];
    const float* b_f2h     = (const float*)d_in[4];
    const float* W_c2h_e   = (const float*)d_in[5];
    const float* b_c2h_e   = (const float*)d_in[6];
    const float* W_mean    = (const float*)d_in[7];
    const float* b_mean    = (const float*)d_in[8];
    const float* W_logvar  = (const float*)d_in[9];
    const float* b_logvar  = (const float*)d_in[10];
    const float* W_z2h     = (const float*)d_in[11];
    const float* b_z2h     = (const float*)d_in[12];
    const float* W_c2h_d   = (const float*)d_in[13];
    const float* b_c2h_d   = (const float*)d_in[14];
    const float* W_out     = (const float*)d_in[15];
    const float* b_out     = (const float*)d_in[16];
    const void*  eidx      = d_in[17];

    int n = in_sizes[0] / 128;
    int e = in_sizes[17] / 2;

    float* oz  = (float*)d_out;
    float* om  = oz  + (size_t)n * 32;
    float* olv = om  + (size_t)n * 32;
    float* oo  = olv + (size_t)n * 32;

    void *pAfc, *pH2, *pHD, *pP, *pAml, *pAz, *pO, *pWml, *pbml;
    cudaGetSymbolAddress(&pAfc, g_Afc);
    cudaGetSymbolAddress(&pH2,  g_H2);
    cudaGetSymbolAddress(&pHD,  g_HD);
    cudaGetSymbolAddress(&pP,   g_P);
    cudaGetSymbolAddress(&pAml, g_Aml);
    cudaGetSymbolAddress(&pAz,  g_Az);
    cudaGetSymbolAddress(&pO,   g_O);
    cudaGetSymbolAddress(&pWml, g_Wml);
    cudaGetSymbolAddress(&pbml, g_bml);
    float* Afc = (float*)pAfc;
    float* H2  = (float*)pH2;
    float* HD  = (float*)pHD;
    float* P   = (float*)pP;
    float* Aml = (float*)pAml;
    float* Az  = (float*)pAz;
    float* O   = (float*)pO;
    float* Wml = (float*)pWml;
    float* bml = (float*)pbml;

    // ---- CSR build ----
    k_zero_deg<<<cdiv(n, 256), 256>>>(n);
    k_detect<<<1, 256>>>((const long long*)eidx, e, n);
    k_convert<<<cdiv(e, 256), 256>>>(eidx, e);
    k_dis<<<cdiv(n, 256), 256>>>(n);
    k_scan<<<1, 1024>>>(n, e);
    k_scatter<<<cdiv(e, 256), 256>>>(e);
    k_pack_wml<<<cdiv(256 * 64, 256), 256>>>(W_mean, W_logvar, b_mean, b_logvar);

    // Pass A: Afc = Agg([feature|condition])  width 192
    k_aggc<32, 16, false><<<cdiv(n * 48, 256), 256>>>(
        (const float4*)feature, (const float4*)condition, nullptr, (float4*)Afc, n);

    // Encoder projections (bias + tanh)
    k_gemm8<128, 128, true, true><<<cdiv(n, 128), 256>>>(Afc,       192, W_f2h,   b_f2h,   H2,       256, n);
    k_gemm8< 64, 128, true, true><<<cdiv(n, 128), 256>>>(Afc + 128, 192, W_c2h_e, b_c2h_e, H2 + 128, 256, n);
    k_gemm8< 64, 128, true, true><<<cdiv(n, 128), 256>>>(Afc + 128, 192, W_c2h_d, b_c2h_d, HD + 128, 256, n);

    // mean+logvar fused projection
    k_gemm8<256, 64, false, false><<<cdiv(n, 256), 256>>>(H2, 256, Wml, nullptr, P, 64, n);

    // Pass B: Aml = Agg(P) + bml  width 64, then z / mean / logvar
    k_aggc<16, 0, true><<<cdiv(n * 16, 256), 256>>>(
        (const float4*)P, nullptr, (const float4*)bml, (float4*)Aml, n);
    k_z<<<cdiv(n * 32, 256), 256>>>(noise, oz, om, olv, n);

    // Pass C: Az = Agg(z)  width 32
    k_aggc<8, 0, false><<<cdiv(n * 8, 256), 256>>>(
        (const float4*)oz, nullptr, nullptr, (float4*)Az, n);

    // Decoder
    k_gemm8< 32, 128, true,  true ><<<cdiv(n, 128), 256>>>(Az, 32,  W_z2h, b_z2h, HD, 256, n);
    k_gemm8<256, 128, false, false><<<cdiv(n, 128), 256>>>(HD, 256, W_out, nullptr, O, 128, n);

    // Pass D: out = Agg(O) + b_out  width 128
    k_aggc<32, 0, true><<<cdiv(n * 32, 256), 256>>>(
        (const float4*)O, nullptr, (const float4*)b_out, (float4*)oo, n);
}